// round 7
// baseline (speedup 1.0000x reference)
#include <cuda_runtime.h>
#include <cuda_bf16.h>
#include <cstdint>
#include <math.h>

#define BATCH 8
#define CH 256
#define MSP 16384          // H*W
#define MAT (CH * CH)      // 65536
#define KSG 4              // gram K-split
#define KLOC (MSP / KSG)   // 4096
#define KCH 32             // gram k per pipeline chunk
#define NCH (KLOC / KCH)   // 128
#define ASTR 40            // gram smem row stride (bf16): conflict-free ldmatrix
#define SBYT (128 * ASTR * 2)          // gram stage bytes (per operand)
#define GRAM_DSMEM (3 * SBYT * 2)      // 3 stages x 2 operands = 61440 B
#define NSTR 72            // NS smem row stride (bf16)
#define NS_STAGE (64 * NSTR)

// ---------------- device scratch (no allocations allowed) ----------------
__device__ __nv_bfloat16 g_hi[(size_t)BATCH * CH * MSP];
__device__ __nv_bfloat16 g_lo[(size_t)BATCH * CH * MSP];
__device__ float g_g1p[KSG][BATCH * MAT];
__device__ float g_g2p[KSG][BATCH * MAT];
__device__ float g_cov[BATCH * MAT];
__device__ float g_mu[BATCH * CH];
__device__ float g_fpart[BATCH][256];
__device__ float g_invN[BATCH];
__device__ float g_rs[BATCH];
__device__ float g_P[5][BATCH * MAT];          // fp32 P_k snapshots for u-chain
__device__ __nv_bfloat16 g_Ph[2][BATCH * MAT]; // split operands (double buffered)
__device__ __nv_bfloat16 g_Pl[2][BATCH * MAT];
__device__ __nv_bfloat16 g_Th[2][BATCH * MAT];
__device__ __nv_bfloat16 g_Tl[2][BATCH * MAT];
__device__ __nv_bfloat16 g_Qh[BATCH * MAT];
__device__ __nv_bfloat16 g_Ql[BATCH * MAT];
__device__ float g_gate[BATCH * CH];

// ---------------- PTX helpers (baseline ISA only) ----------------
__device__ __forceinline__ uint32_t smem_u32(const void* p) {
    uint32_t a;
    asm("{ .reg .u64 t; cvta.to.shared.u64 t, %1; cvt.u32.u64 %0, t; }"
        : "=r"(a) : "l"(p));
    return a;
}
#define CP_ASYNC16(dst, src) \
    asm volatile("cp.async.cg.shared.global [%0], [%1], 16;" :: "r"(dst), "l"(src))
#define CP_COMMIT() asm volatile("cp.async.commit_group;" ::: "memory")
#define CP_WAIT1() asm volatile("cp.async.wait_group 1;" ::: "memory")

__device__ __forceinline__ void ldm_x4(uint32_t* r, uint32_t addr) {
    asm volatile("ldmatrix.sync.aligned.m8n8.x4.shared.b16 {%0,%1,%2,%3}, [%4];"
                 : "=r"(r[0]), "=r"(r[1]), "=r"(r[2]), "=r"(r[3]) : "r"(addr));
}
__device__ __forceinline__ void ldm_x2(uint32_t* r, uint32_t addr) {
    asm volatile("ldmatrix.sync.aligned.m8n8.x2.shared.b16 {%0,%1}, [%2];"
                 : "=r"(r[0]), "=r"(r[1]) : "r"(addr));
}
__device__ __forceinline__ void mma_bf16(float* c, const uint32_t* a, const uint32_t* b) {
    asm volatile(
        "mma.sync.aligned.m16n8k16.row.col.f32.bf16.bf16.f32 "
        "{%0,%1,%2,%3}, {%4,%5,%6,%7}, {%8,%9}, {%0,%1,%2,%3};"
        : "+f"(c[0]), "+f"(c[1]), "+f"(c[2]), "+f"(c[3])
        : "r"(a[0]), "r"(a[1]), "r"(a[2]), "r"(a[3]), "r"(b[0]), "r"(b[1]));
}

// ---------------- helpers ----------------
__device__ __forceinline__ float blockReduceSum256(float v) {
    __shared__ float sh[8];
    int lane = threadIdx.x & 31, w = threadIdx.x >> 5;
#pragma unroll
    for (int o = 16; o; o >>= 1) v += __shfl_down_sync(0xffffffffu, v, o);
    if (lane == 0) sh[w] = v;
    __syncthreads();
    if (threadIdx.x < 32) {
        v = (threadIdx.x < 8) ? sh[threadIdx.x] : 0.f;
#pragma unroll
        for (int o = 4; o; o >>= 1) v += __shfl_down_sync(0xffffffffu, v, o);
    }
    return v;  // valid in thread 0
}

// ---------------- fused: bf16 hi/lo split + per-(b,c) spatial mean ----------------
__global__ void __launch_bounds__(256) convert_kernel(const float* __restrict__ x) {
    int bc = blockIdx.x;  // 0..2047
    const float4* p = (const float4*)(x + (size_t)bc * MSP);
    __nv_bfloat162* hi2 = (__nv_bfloat162*)g_hi + (size_t)bc * (MSP / 2);
    __nv_bfloat162* lo2 = (__nv_bfloat162*)g_lo + (size_t)bc * (MSP / 2);
    float s = 0.f;
    for (int t = threadIdx.x; t < MSP / 4; t += 256) {
        float4 v = p[t];
        s += v.x + v.y + v.z + v.w;
        __nv_bfloat16 h0 = __float2bfloat16(v.x);
        __nv_bfloat16 h1 = __float2bfloat16(v.y);
        __nv_bfloat16 h2 = __float2bfloat16(v.z);
        __nv_bfloat16 h3 = __float2bfloat16(v.w);
        __nv_bfloat16 l0 = __float2bfloat16(v.x - __bfloat162float(h0));
        __nv_bfloat16 l1 = __float2bfloat16(v.y - __bfloat162float(h1));
        __nv_bfloat16 l2 = __float2bfloat16(v.z - __bfloat162float(h2));
        __nv_bfloat16 l3 = __float2bfloat16(v.w - __bfloat162float(h3));
        __nv_bfloat162 a, b, c, d;
        a.x = h0; a.y = h1; b.x = h2; b.y = h3;
        c.x = l0; c.y = l1; d.x = l2; d.y = l3;
        hi2[t * 2] = a; hi2[t * 2 + 1] = b;
        lo2[t * 2] = c; lo2[t * 2 + 1] = d;
    }
    s = blockReduceSum256(s);
    if (threadIdx.x == 0) g_mu[bc] = s * (1.f / MSP);
}

// ---------------- Gram via HMMA, 3-stage cp.async ring (1 sync per chunk) -------
__global__ void __launch_bounds__(256, 1) gram_hmma_kernel() {
    extern __shared__ __nv_bfloat16 gsm[];
    uint32_t sA0 = smem_u32(gsm);
    uint32_t sB0 = sA0 + 3 * SBYT;

    int tid = threadIdx.x, wid = tid >> 5, lane = tid & 31;
    int pair = blockIdx.x, ks = blockIdx.y, b = blockIdx.z;
    int mat = (pair >= 3);
    int t = mat ? (pair - 3) : pair;
    int ti, tj;
    if (mat) { ti = t >> 1; tj = t & 1; }
    else     { ti = (t == 2) ? 1 : 0; tj = (t == 0) ? 0 : 1; }

    const __nv_bfloat16* Ag =
        g_hi + ((size_t)b * CH + (size_t)ti * 128) * MSP + (size_t)ks * KLOC;
    const __nv_bfloat16* Bg =
        (mat ? g_lo : g_hi) + ((size_t)b * CH + (size_t)tj * 128) * MSP + (size_t)ks * KLOC;

    int lr = tid >> 1;
    int lf = (tid & 1) * 2;
    uint32_t dstA = sA0 + (uint32_t)(lr * ASTR + lf * 8) * 2;
    uint32_t dstB = sB0 + (uint32_t)(lr * ASTR + lf * 8) * 2;
    const __nv_bfloat16* Arow = Ag + (size_t)lr * MSP + lf * 8;
    const __nv_bfloat16* Brow = Bg + (size_t)lr * MSP + lf * 8;

    int warp_m = wid >> 2, warp_n = wid & 3;
    uint32_t a_off[4], b_off[4];
#pragma unroll
    for (int mt = 0; mt < 4; mt++) {
        int row = warp_m * 64 + mt * 16 + (lane & 15);
        a_off[mt] = (uint32_t)(row * ASTR + (lane >> 4) * 8) * 2;
    }
#pragma unroll
    for (int nt = 0; nt < 4; nt++) {
        int l2 = lane & 15;
        int row = warp_n * 32 + nt * 8 + (l2 & 7);
        b_off[nt] = (uint32_t)(row * ASTR + (l2 >> 3) * 8) * 2;
    }

    float acc[4][4][4];
#pragma unroll
    for (int i = 0; i < 4; i++)
#pragma unroll
        for (int j = 0; j < 4; j++)
#pragma unroll
            for (int k = 0; k < 4; k++) acc[i][j][k] = 0.f;

    // prologue: chunks 0,1 into stages 0,1 (one commit group each)
#pragma unroll
    for (int p = 0; p < 2; p++) {
        CP_ASYNC16(dstA + p * SBYT, Arow + p * KCH);
        CP_ASYNC16(dstA + p * SBYT + 16, Arow + p * KCH + 8);
        CP_ASYNC16(dstB + p * SBYT, Brow + p * KCH);
        CP_ASYNC16(dstB + p * SBYT + 16, Brow + p * KCH + 8);
        CP_COMMIT();
    }

    int st = 0;    // stage of chunk c
    int stp = 2;   // stage of chunk c+2
    for (int c = 0; c < NCH; c++) {
        CP_WAIT1();         // <=1 group pending -> chunk c resident
        __syncthreads();    // all warps done reading stage stp (their iter c-1)
        if (c + 2 < NCH) {
            const __nv_bfloat16* Ap = Arow + (c + 2) * KCH;
            const __nv_bfloat16* Bp = Brow + (c + 2) * KCH;
            CP_ASYNC16(dstA + stp * SBYT, Ap);
            CP_ASYNC16(dstA + stp * SBYT + 16, Ap + 8);
            CP_ASYNC16(dstB + stp * SBYT, Bp);
            CP_ASYNC16(dstB + stp * SBYT + 16, Bp + 8);
        }
        CP_COMMIT();

        uint32_t baseA = sA0 + st * SBYT;
        uint32_t baseB = sB0 + st * SBYT;
#pragma unroll
        for (int kh = 0; kh < 2; kh++) {
            uint32_t af[4][4], bf[4][2];
#pragma unroll
            for (int mt = 0; mt < 4; mt++) ldm_x4(af[mt], baseA + a_off[mt] + kh * 32);
#pragma unroll
            for (int nt = 0; nt < 4; nt++) ldm_x2(bf[nt], baseB + b_off[nt] + kh * 32);
#pragma unroll
            for (int mt = 0; mt < 4; mt++)
#pragma unroll
                for (int nt = 0; nt < 4; nt++) mma_bf16(acc[mt][nt], af[mt], bf[nt]);
        }
        st = (st == 2) ? 0 : st + 1;
        stp = (stp == 2) ? 0 : stp + 1;
    }

    float* dst = (mat ? g_g2p[ks] : g_g1p[ks]) + (size_t)b * MAT;
    int grp = lane >> 2, qp = lane & 3;
#pragma unroll
    for (int mt = 0; mt < 4; mt++) {
        int row0 = ti * 128 + warp_m * 64 + mt * 16;
#pragma unroll
        for (int nt = 0; nt < 4; nt++) {
            int col0 = tj * 128 + warp_n * 32 + nt * 8 + qp * 2;
            float2 v0 = make_float2(acc[mt][nt][0], acc[mt][nt][1]);
            float2 v1 = make_float2(acc[mt][nt][2], acc[mt][nt][3]);
            *(float2*)(dst + (size_t)(row0 + grp) * CH + col0) = v0;
            *(float2*)(dst + (size_t)(row0 + grp + 8) * CH + col0) = v1;
        }
    }
}

// ---------------- reduce partials -> centered covariance (+frobenius partials) ----
__global__ void __launch_bounds__(256) cov_reduce_kernel() {
    int b = blockIdx.y;
    int idx = blockIdx.x * 256 + threadIdx.x;
    int i = idx >> 8, j = idx & 255;
    int si = (i <= j) ? i : j;
    int sj = (i <= j) ? j : i;
    float s = 0.f;
#pragma unroll
    for (int ks = 0; ks < KSG; ks++) {
        s += g_g1p[ks][(size_t)b * MAT + si * CH + sj];
        s += g_g2p[ks][(size_t)b * MAT + idx];
        s += g_g2p[ks][(size_t)b * MAT + j * CH + i];
    }
    float v = s * (1.f / MSP) - g_mu[b * CH + i] * g_mu[b * CH + j];
    g_cov[(size_t)b * MAT + idx] = v;
    float sq = blockReduceSum256(v * v);
    if (threadIdx.x == 0) g_fpart[b][blockIdx.x] = sq;
}

// ---------------- finalize frobenius norm ----------------
__global__ void __launch_bounds__(256) frob2_kernel() {
    int b = blockIdx.x;
    float s = blockReduceSum256(g_fpart[b][threadIdx.x]);
    if (threadIdx.x == 0) {
        float n = sqrtf(s);
        g_invN[b] = 1.f / n;
        g_rs[b] = rsqrtf(n);
    }
}

// ---------------- init: P0 = cov/normA; write fp32 snapshot + splits of P0,T0 ----
__global__ void __launch_bounds__(256) init_kernel() {
    int b = blockIdx.y;
    int idx = blockIdx.x * 256 + threadIdx.x;
    size_t o = (size_t)b * MAT + idx;
    float v = g_cov[o] * g_invN[b];
    g_P[0][o] = v;
    __nv_bfloat16 ph = __float2bfloat16(v);
    g_Ph[0][o] = ph;
    g_Pl[0][o] = __float2bfloat16(v - __bfloat162float(ph));
    int i = idx >> 8, j = idx & 255;
    float tv = ((i == j) ? 1.5f : 0.f) - 0.5f * v;
    __nv_bfloat16 th = __float2bfloat16(tv);
    g_Th[0][o] = th;
    g_Tl[0][o] = __float2bfloat16(tv - __bfloat162float(th));
}

// ---------------- NS matmul via HMMA: C = A.B^T (symmetric operands, split bf16) --
// 64x64 tile/CTA, 128 thr, K = 3 terms x 256. Epilogue: split C; optionally also
// write T(C) splits and fp32 C snapshot.
__device__ __forceinline__ void ns_mm_body(
    const __nv_bfloat16* __restrict__ Ah, const __nv_bfloat16* __restrict__ Al,
    const __nv_bfloat16* __restrict__ Bh, const __nv_bfloat16* __restrict__ Bl,
    __nv_bfloat16* __restrict__ Ch, __nv_bfloat16* __restrict__ Cl,
    __nv_bfloat16* __restrict__ Thd, __nv_bfloat16* __restrict__ Tld,
    float* __restrict__ Pf) {
    __shared__ __nv_bfloat16 sA[2][NS_STAGE];
    __shared__ __nv_bfloat16 sB[2][NS_STAGE];
    int bb = blockIdx.y;
    size_t boff = (size_t)bb * MAT;
    int ti = blockIdx.x >> 2, tj = blockIdx.x & 3;
    int tid = threadIdx.x, wid = tid >> 5, lane = tid & 31;
    int warp_m = wid & 1, warp_n = wid >> 1;

    const __nv_bfloat16* As[3] = {Ah + boff, Ah + boff, Al + boff};
    const __nv_bfloat16* Bs[3] = {Bh + boff, Bl + boff, Bh + boff};

    uint32_t sA0 = smem_u32(&sA[0][0]), sB0 = smem_u32(&sB[0][0]);
    const uint32_t stage = NS_STAGE * 2;

    int lr = tid >> 1;
    int lsp = (tid & 1) * 4;
    uint32_t dA = sA0 + (uint32_t)(lr * NSTR + lsp * 8) * 2;
    uint32_t dB = sB0 + (uint32_t)(lr * NSTR + lsp * 8) * 2;

    uint32_t a_off[2], b_off[2];
#pragma unroll
    for (int mt = 0; mt < 2; mt++) {
        int row = warp_m * 32 + mt * 16 + (lane & 15);
        a_off[mt] = (uint32_t)(row * NSTR + (lane >> 4) * 8) * 2;
    }
#pragma unroll
    for (int np = 0; np < 2; np++) {
        int row = warp_n * 32 + np * 16 + (lane >> 4) * 8 + (lane & 7);
        b_off[np] = (uint32_t)(row * NSTR + ((lane >> 3) & 1) * 8) * 2;
    }

    float acc[2][4][4];
#pragma unroll
    for (int i = 0; i < 2; i++)
#pragma unroll
        for (int j = 0; j < 4; j++)
#pragma unroll
            for (int k = 0; k < 4; k++) acc[i][j][k] = 0.f;

    {
        const __nv_bfloat16* Ap = As[0] + (size_t)(ti * 64 + lr) * CH + lsp * 8;
        const __nv_bfloat16* Bp = Bs[0] + (size_t)(tj * 64 + lr) * CH + lsp * 8;
#pragma unroll
        for (int s4 = 0; s4 < 4; s4++) {
            CP_ASYNC16(dA + s4 * 16, Ap + s4 * 8);
            CP_ASYNC16(dB + s4 * 16, Bp + s4 * 8);
        }
        CP_COMMIT();
    }

    for (int c = 0; c < 12; c++) {
        int s = c & 1;
        if (c + 1 < 12) {
            int t1 = (c + 1) >> 2, kk1 = ((c + 1) & 3) * 64;
            int sn = (c + 1) & 1;
            const __nv_bfloat16* Ap = As[t1] + (size_t)(ti * 64 + lr) * CH + kk1 + lsp * 8;
            const __nv_bfloat16* Bp = Bs[t1] + (size_t)(tj * 64 + lr) * CH + kk1 + lsp * 8;
#pragma unroll
            for (int s4 = 0; s4 < 4; s4++) {
                CP_ASYNC16(dA + sn * stage + s4 * 16, Ap + s4 * 8);
                CP_ASYNC16(dB + sn * stage + s4 * 16, Bp + s4 * 8);
            }
        }
        CP_COMMIT();
        CP_WAIT1();
        __syncthreads();

        uint32_t bA = sA0 + s * stage, bB = sB0 + s * stage;
#pragma unroll
        for (int kh = 0; kh < 4; kh++) {
            uint32_t af[2][4], bfr[2][4];
#pragma unroll
            for (int mt = 0; mt < 2; mt++) ldm_x4(af[mt], bA + a_off[mt] + kh * 32);
#pragma unroll
            for (int np = 0; np < 2; np++) ldm_x4(bfr[np], bB + b_off[np] + kh * 32);
#pragma unroll
            for (int mt = 0; mt < 2; mt++)
#pragma unroll
                for (int nt = 0; nt < 4; nt++)
                    mma_bf16(acc[mt][nt], af[mt], &bfr[nt >> 1][(nt & 1) * 2]);
        }
        __syncthreads();
    }

    int grp = lane >> 2, qp = lane & 3;
#pragma unroll
    for (int mt = 0; mt < 2; mt++)
#pragma unroll
        for (int half = 0; half < 2; half++) {
            int row = ti * 64 + warp_m * 32 + mt * 16 + grp + half * 8;
#pragma unroll
            for (int nt = 0; nt < 4; nt++) {
                int col = tj * 64 + warp_n * 32 + nt * 8 + qp * 2;
                float v0 = acc[mt][nt][half * 2];
                float v1 = acc[mt][nt][half * 2 + 1];
                size_t o = boff + (size_t)row * CH + col;
                __nv_bfloat16 h0 = __float2bfloat16(v0);
                __nv_bfloat16 h1 = __float2bfloat16(v1);
                __nv_bfloat162 hv, lv;
                hv.x = h0; hv.y = h1;
                lv.x = __float2bfloat16(v0 - __bfloat162float(h0));
                lv.y = __float2bfloat16(v1 - __bfloat162float(h1));
                *(__nv_bfloat162*)(Ch + o) = hv;
                *(__nv_bfloat162*)(Cl + o) = lv;
                if (Thd) {
                    float t0 = ((row == col) ? 1.5f : 0.f) - 0.5f * v0;
                    float t1 = ((row == col + 1) ? 1.5f : 0.f) - 0.5f * v1;
                    __nv_bfloat16 th0 = __float2bfloat16(t0);
                    __nv_bfloat16 th1 = __float2bfloat16(t1);
                    __nv_bfloat162 tv2, tl2;
                    tv2.x = th0; tv2.y = th1;
                    tl2.x = __float2bfloat16(t0 - __bfloat162float(th0));
                    tl2.y = __float2bfloat16(t1 - __bfloat162float(th1));
                    *(__nv_bfloat162*)(Thd + o) = tv2;
                    *(__nv_bfloat162*)(Tld + o) = tl2;
                    *(float2*)(Pf + o) = make_float2(v0, v1);
                }
            }
        }
}

// Q = T_k . P_k
__global__ void __launch_bounds__(128) nsQ_kernel(int cur) {
    ns_mm_body(g_Th[cur], g_Tl[cur], g_Ph[cur], g_Pl[cur],
               g_Qh, g_Ql, nullptr, nullptr, nullptr);
}
// P_{k+1} = T_k . Q^T = T_k P_k T_k ; epilogue also emits T_{k+1} splits + fp32 P
__global__ void __launch_bounds__(128) nsP_kernel(int cur, int k) {
    ns_mm_body(g_Th[cur], g_Tl[cur], g_Qh, g_Ql,
               g_Ph[cur ^ 1], g_Pl[cur ^ 1], g_Th[cur ^ 1], g_Tl[cur ^ 1], g_P[k + 1]);
}

// ---------------- fused u-chain (Z5 . 1) + rowmean scaling + SE MLP ----------------
__global__ void __launch_bounds__(256) uchain_se_kernel(
    const float* __restrict__ w1, const float* __restrict__ b1,
    const float* __restrict__ w2, const float* __restrict__ b2) {
    int b = blockIdx.x, c = threadIdx.x;
    __shared__ float u[CH];
    __shared__ float hs[32];
    u[c] = 1.f;
    __syncthreads();
#pragma unroll
    for (int k = 0; k < 5; k++) {
        const float* P = g_P[k] + (size_t)b * MAT;
        float s = 0.f;
#pragma unroll 8
        for (int j = 0; j < CH; j++)  // column read == row read (P symmetric)
            s = fmaf(P[(size_t)j * CH + c], u[j], s);
        float nu = 1.5f * u[c] - 0.5f * s;
        __syncthreads();
        u[c] = nu;
        __syncthreads();
    }
    float y = u[c] * (1.f / CH) * g_rs[b];
    __syncthreads();
    u[c] = y;
    __syncthreads();
    if (c < 32) {
        float s = b1[c];
        const float* w = w1 + c * CH;
#pragma unroll 8
        for (int j = 0; j < CH; j++) s = fmaf(u[j], w[j], s);
        hs[c] = fmaxf(s, 0.f);
    }
    __syncthreads();
    float s = b2[c];
    const float* w = w2 + c * 32;
#pragma unroll
    for (int j = 0; j < 32; j++) s = fmaf(hs[j], w[j], s);
    g_gate[b * CH + c] = 1.f / (1.f + expf(-s));
}

// ---------------- out = x * gate[b,c] ----------------
__global__ void __launch_bounds__(256) scale_kernel(const float* __restrict__ x,
                                                    float* __restrict__ out) {
    const float4* xi = (const float4*)x;
    float4* oo = (float4*)out;
    const size_t total = (size_t)BATCH * CH * MSP / 4;
    for (size_t i = (size_t)blockIdx.x * blockDim.x + threadIdx.x; i < total;
         i += (size_t)gridDim.x * blockDim.x) {
        float g = g_gate[i >> 12];
        float4 v = xi[i];
        v.x *= g; v.y *= g; v.z *= g; v.w *= g;
        oo[i] = v;
    }
}

// ---------------- launch ----------------
extern "C" void kernel_launch(void* const* d_in, const int* in_sizes, int n_in,
                              void* d_out, int out_size) {
    const float* x = (const float*)d_in[0];
    const float* w1 = (const float*)d_in[1];
    const float* b1 = (const float*)d_in[2];
    const float* w2 = (const float*)d_in[3];
    const float* b2 = (const float*)d_in[4];
    float* out = (float*)d_out;

    cudaFuncSetAttribute(gram_hmma_kernel, cudaFuncAttributeMaxDynamicSharedMemorySize,
                         GRAM_DSMEM);

    convert_kernel<<<BATCH * CH, 256>>>(x);
    gram_hmma_kernel<<<dim3(7, KSG, BATCH), 256, GRAM_DSMEM>>>();
    cov_reduce_kernel<<<dim3(256, BATCH), 256>>>();
    frob2_kernel<<<BATCH, 256>>>();
    init_kernel<<<dim3(256, BATCH), 256>>>();

    int cur = 0;
    for (int k = 0; k < 4; k++) {
        nsQ_kernel<<<dim3(16, BATCH), 128>>>(cur);
        nsP_kernel<<<dim3(16, BATCH), 128>>>(cur, k);
        cur ^= 1;
    }

    uchain_se_kernel<<<BATCH, 256>>>(w1, b1, w2, b2);
    scale_kernel<<<8192, 256>>>(x, out);
}

// round 8
// speedup vs baseline: 1.1310x; 1.1310x over previous
#include <cuda_runtime.h>
#include <cuda_bf16.h>
#include <cstdint>
#include <math.h>

#define BATCH 8
#define CH 256
#define MSP 16384          // H*W
#define MAT (CH * CH)      // 65536
#define KSG 8              // gram K-split: 7*8*8=448 CTAs -> balanced 2/SM waves
#define KLOC (MSP / KSG)   // 2048
#define KCH 32             // gram k per pipeline chunk
#define NCH (KLOC / KCH)   // 64
#define ASTR 40            // gram smem row stride (bf16): conflict-free ldmatrix
#define NSTR 72            // NS smem row stride (bf16)
#define NS_STAGE (64 * NSTR)

// ---------------- device scratch (no allocations allowed) ----------------
__device__ __nv_bfloat16 g_hi[(size_t)BATCH * CH * MSP];
__device__ __nv_bfloat16 g_lo[(size_t)BATCH * CH * MSP];
__device__ float g_g1p[KSG][BATCH * MAT];
__device__ float g_g2p[KSG][BATCH * MAT];
__device__ float g_cov[BATCH * MAT];
__device__ float g_mu[BATCH * CH];
__device__ float g_fpart[BATCH][256];
__device__ float g_rs[BATCH];
__device__ __nv_bfloat16 g_Yh[2][BATCH * MAT];
__device__ __nv_bfloat16 g_Yl[2][BATCH * MAT];
__device__ __nv_bfloat16 g_Zh[2][BATCH * MAT];
__device__ __nv_bfloat16 g_Zl[2][BATCH * MAT];
__device__ __nv_bfloat16 g_Th[BATCH * MAT];
__device__ __nv_bfloat16 g_Tl[BATCH * MAT];
__device__ float g_Zf[BATCH * MAT];
__device__ float g_gate[BATCH * CH];

// ---------------- PTX helpers (baseline ISA only) ----------------
__device__ __forceinline__ uint32_t smem_u32(const void* p) {
    uint32_t a;
    asm("{ .reg .u64 t; cvta.to.shared.u64 t, %1; cvt.u32.u64 %0, t; }"
        : "=r"(a) : "l"(p));
    return a;
}
#define CP_ASYNC16(dst, src) \
    asm volatile("cp.async.cg.shared.global [%0], [%1], 16;" :: "r"(dst), "l"(src))
#define CP_COMMIT() asm volatile("cp.async.commit_group;" ::: "memory")
#define CP_WAIT1() asm volatile("cp.async.wait_group 1;" ::: "memory")

__device__ __forceinline__ void ldm_x4(uint32_t* r, uint32_t addr) {
    asm volatile("ldmatrix.sync.aligned.m8n8.x4.shared.b16 {%0,%1,%2,%3}, [%4];"
                 : "=r"(r[0]), "=r"(r[1]), "=r"(r[2]), "=r"(r[3]) : "r"(addr));
}
__device__ __forceinline__ void ldm_x2(uint32_t* r, uint32_t addr) {
    asm volatile("ldmatrix.sync.aligned.m8n8.x2.shared.b16 {%0,%1}, [%2];"
                 : "=r"(r[0]), "=r"(r[1]) : "r"(addr));
}
__device__ __forceinline__ void mma_bf16(float* c, const uint32_t* a, const uint32_t* b) {
    asm volatile(
        "mma.sync.aligned.m16n8k16.row.col.f32.bf16.bf16.f32 "
        "{%0,%1,%2,%3}, {%4,%5,%6,%7}, {%8,%9}, {%0,%1,%2,%3};"
        : "+f"(c[0]), "+f"(c[1]), "+f"(c[2]), "+f"(c[3])
        : "r"(a[0]), "r"(a[1]), "r"(a[2]), "r"(a[3]), "r"(b[0]), "r"(b[1]));
}

// ---------------- helpers ----------------
__device__ __forceinline__ float blockReduceSum256(float v) {
    __shared__ float sh[8];
    int lane = threadIdx.x & 31, w = threadIdx.x >> 5;
#pragma unroll
    for (int o = 16; o; o >>= 1) v += __shfl_down_sync(0xffffffffu, v, o);
    if (lane == 0) sh[w] = v;
    __syncthreads();
    if (threadIdx.x < 32) {
        v = (threadIdx.x < 8) ? sh[threadIdx.x] : 0.f;
#pragma unroll
        for (int o = 4; o; o >>= 1) v += __shfl_down_sync(0xffffffffu, v, o);
    }
    return v;  // valid in thread 0
}

// ---------------- fused: bf16 hi/lo split + per-(b,c) spatial mean ----------------
__global__ void __launch_bounds__(256) convert_kernel(const float* __restrict__ x) {
    int bc = blockIdx.x;  // 0..2047
    const float4* p = (const float4*)(x + (size_t)bc * MSP);
    __nv_bfloat162* hi2 = (__nv_bfloat162*)g_hi + (size_t)bc * (MSP / 2);
    __nv_bfloat162* lo2 = (__nv_bfloat162*)g_lo + (size_t)bc * (MSP / 2);
    float s = 0.f;
    for (int t = threadIdx.x; t < MSP / 4; t += 256) {
        float4 v = p[t];
        s += v.x + v.y + v.z + v.w;
        __nv_bfloat16 h0 = __float2bfloat16(v.x);
        __nv_bfloat16 h1 = __float2bfloat16(v.y);
        __nv_bfloat16 h2 = __float2bfloat16(v.z);
        __nv_bfloat16 h3 = __float2bfloat16(v.w);
        __nv_bfloat16 l0 = __float2bfloat16(v.x - __bfloat162float(h0));
        __nv_bfloat16 l1 = __float2bfloat16(v.y - __bfloat162float(h1));
        __nv_bfloat16 l2 = __float2bfloat16(v.z - __bfloat162float(h2));
        __nv_bfloat16 l3 = __float2bfloat16(v.w - __bfloat162float(h3));
        __nv_bfloat162 a, b, c, d;
        a.x = h0; a.y = h1; b.x = h2; b.y = h3;
        c.x = l0; c.y = l1; d.x = l2; d.y = l3;
        hi2[t * 2] = a; hi2[t * 2 + 1] = b;
        lo2[t * 2] = c; lo2[t * 2 + 1] = d;
    }
    s = blockReduceSum256(s);
    if (threadIdx.x == 0) g_mu[bc] = s * (1.f / MSP);
}

// ---------------- Gram via HMMA (R6 2-stage pipeline, KSG=8 for balance) --------
__global__ void __launch_bounds__(256, 2) gram_hmma_kernel() {
    __shared__ __nv_bfloat16 sA[2][128 * ASTR];
    __shared__ __nv_bfloat16 sB[2][128 * ASTR];

    int tid = threadIdx.x, wid = tid >> 5, lane = tid & 31;
    int pair = blockIdx.x, ks = blockIdx.y, b = blockIdx.z;
    int mat = (pair >= 3);
    int t = mat ? (pair - 3) : pair;
    int ti, tj;
    if (mat) { ti = t >> 1; tj = t & 1; }
    else     { ti = (t == 2) ? 1 : 0; tj = (t == 0) ? 0 : 1; }

    const __nv_bfloat16* Ag =
        g_hi + ((size_t)b * CH + (size_t)ti * 128) * MSP + (size_t)ks * KLOC;
    const __nv_bfloat16* Bg =
        (mat ? g_lo : g_hi) + ((size_t)b * CH + (size_t)tj * 128) * MSP + (size_t)ks * KLOC;

    uint32_t sA0 = smem_u32(&sA[0][0]);
    uint32_t sB0 = smem_u32(&sB[0][0]);
    const uint32_t stageA = 128 * ASTR * 2;
    const uint32_t stageB = 128 * ASTR * 2;

    int lr = tid >> 1;
    int lf = (tid & 1) * 2;
    uint32_t dstA = sA0 + (uint32_t)(lr * ASTR + lf * 8) * 2;
    uint32_t dstB = sB0 + (uint32_t)(lr * ASTR + lf * 8) * 2;

    int warp_m = wid >> 2, warp_n = wid & 3;
    uint32_t a_off[4], b_off[4];
#pragma unroll
    for (int mt = 0; mt < 4; mt++) {
        int row = warp_m * 64 + mt * 16 + (lane & 15);
        a_off[mt] = (uint32_t)(row * ASTR + (lane >> 4) * 8) * 2;
    }
#pragma unroll
    for (int nt = 0; nt < 4; nt++) {
        int l2 = lane & 15;
        int row = warp_n * 32 + nt * 8 + (l2 & 7);
        b_off[nt] = (uint32_t)(row * ASTR + (l2 >> 3) * 8) * 2;
    }

    float acc[4][4][4];
#pragma unroll
    for (int i = 0; i < 4; i++)
#pragma unroll
        for (int j = 0; j < 4; j++)
#pragma unroll
            for (int k = 0; k < 4; k++) acc[i][j][k] = 0.f;

    {
        const __nv_bfloat16* Ap = Ag + (size_t)lr * MSP + lf * 8;
        const __nv_bfloat16* Bp = Bg + (size_t)lr * MSP + lf * 8;
        CP_ASYNC16(dstA, Ap); CP_ASYNC16(dstA + 16, Ap + 8);
        CP_ASYNC16(dstB, Bp); CP_ASYNC16(dstB + 16, Bp + 8);
        CP_COMMIT();
    }

    for (int c = 0; c < NCH; c++) {
        int s = c & 1;
        if (c + 1 < NCH) {
            int sn = (c + 1) & 1;
            const __nv_bfloat16* Ap = Ag + (size_t)lr * MSP + (c + 1) * KCH + lf * 8;
            const __nv_bfloat16* Bp = Bg + (size_t)lr * MSP + (c + 1) * KCH + lf * 8;
            CP_ASYNC16(dstA + sn * stageA, Ap); CP_ASYNC16(dstA + sn * stageA + 16, Ap + 8);
            CP_ASYNC16(dstB + sn * stageB, Bp); CP_ASYNC16(dstB + sn * stageB + 16, Bp + 8);
        }
        CP_COMMIT();
        CP_WAIT1();
        __syncthreads();

        uint32_t baseA = sA0 + s * stageA;
        uint32_t baseB = sB0 + s * stageB;
#pragma unroll
        for (int kh = 0; kh < 2; kh++) {
            uint32_t af[4][4], bf[4][2];
#pragma unroll
            for (int mt = 0; mt < 4; mt++) ldm_x4(af[mt], baseA + a_off[mt] + kh * 32);
#pragma unroll
            for (int nt = 0; nt < 4; nt++) ldm_x2(bf[nt], baseB + b_off[nt] + kh * 32);
#pragma unroll
            for (int mt = 0; mt < 4; mt++)
#pragma unroll
                for (int nt = 0; nt < 4; nt++) mma_bf16(acc[mt][nt], af[mt], bf[nt]);
        }
        __syncthreads();
    }

    float* dst = (mat ? g_g2p[ks] : g_g1p[ks]) + (size_t)b * MAT;
    int grp = lane >> 2, qp = lane & 3;
#pragma unroll
    for (int mt = 0; mt < 4; mt++) {
        int row0 = ti * 128 + warp_m * 64 + mt * 16;
#pragma unroll
        for (int nt = 0; nt < 4; nt++) {
            int col0 = tj * 128 + warp_n * 32 + nt * 8 + qp * 2;
            float2 v0 = make_float2(acc[mt][nt][0], acc[mt][nt][1]);
            float2 v1 = make_float2(acc[mt][nt][2], acc[mt][nt][3]);
            *(float2*)(dst + (size_t)(row0 + grp) * CH + col0) = v0;
            *(float2*)(dst + (size_t)(row0 + grp + 8) * CH + col0) = v1;
        }
    }
}

// ---------------- reduce partials -> centered covariance (+frobenius partials) ----
__global__ void __launch_bounds__(256) cov_reduce_kernel() {
    int b = blockIdx.y;
    int idx = blockIdx.x * 256 + threadIdx.x;
    int i = idx >> 8, j = idx & 255;
    int si = (i <= j) ? i : j;
    int sj = (i <= j) ? j : i;
    float s = 0.f;
#pragma unroll
    for (int ks = 0; ks < KSG; ks++) {
        s += g_g1p[ks][(size_t)b * MAT + si * CH + sj];
        s += g_g2p[ks][(size_t)b * MAT + idx];
        s += g_g2p[ks][(size_t)b * MAT + j * CH + i];
    }
    float v = s * (1.f / MSP) - g_mu[b * CH + i] * g_mu[b * CH + j];
    g_cov[(size_t)b * MAT + idx] = v;
    float sq = blockReduceSum256(v * v);
    if (threadIdx.x == 0) g_fpart[b][blockIdx.x] = sq;
}

// ---------------- fused frobenius finalize + init Y0 = cov/normA, Z0 = I --------
__global__ void __launch_bounds__(256) init_frob_kernel() {
    __shared__ float tot;
    int b = blockIdx.y;
    float s = blockReduceSum256(g_fpart[b][threadIdx.x]);
    if (threadIdx.x == 0) tot = s;
    __syncthreads();
    float fs = tot;
    float n = sqrtf(fs);
    float inv = 1.f / n;
    if (blockIdx.x == 0 && threadIdx.x == 0) g_rs[b] = rsqrtf(n);

    int idx = blockIdx.x * 256 + threadIdx.x;
    size_t o = (size_t)b * MAT + idx;
    float v = g_cov[o] * inv;
    __nv_bfloat16 h = __float2bfloat16(v);
    g_Yh[0][o] = h;
    g_Yl[0][o] = __float2bfloat16(v - __bfloat162float(h));
    int i = idx >> 8, j = idx & 255;
    g_Zh[0][o] = __float2bfloat16((i == j) ? 1.f : 0.f);
    g_Zl[0][o] = __float2bfloat16(0.f);
}

// ---------------- NS matmul via HMMA: C = A.B (A,B symmetric, split bf16) ------
__device__ __forceinline__ void ns_mm_body(
    const __nv_bfloat16* __restrict__ Ah, const __nv_bfloat16* __restrict__ Al,
    const __nv_bfloat16* __restrict__ Bh, const __nv_bfloat16* __restrict__ Bl,
    __nv_bfloat16* __restrict__ Ch, __nv_bfloat16* __restrict__ Cl,
    float* __restrict__ Cf, bool tEpi) {
    __shared__ __nv_bfloat16 sA[2][NS_STAGE];
    __shared__ __nv_bfloat16 sB[2][NS_STAGE];
    int bb = blockIdx.y;
    size_t boff = (size_t)bb * MAT;
    int ti = blockIdx.x >> 2, tj = blockIdx.x & 3;
    int tid = threadIdx.x, wid = tid >> 5, lane = tid & 31;
    int warp_m = wid & 1, warp_n = wid >> 1;

    const __nv_bfloat16* As[3] = {Ah + boff, Ah + boff, Al + boff};
    const __nv_bfloat16* Bs[3] = {Bh + boff, Bl + boff, Bh + boff};

    uint32_t sA0 = smem_u32(&sA[0][0]), sB0 = smem_u32(&sB[0][0]);
    const uint32_t stage = NS_STAGE * 2;

    int lr = tid >> 1;
    int lsp = (tid & 1) * 4;
    uint32_t dA = sA0 + (uint32_t)(lr * NSTR + lsp * 8) * 2;
    uint32_t dB = sB0 + (uint32_t)(lr * NSTR + lsp * 8) * 2;

    uint32_t a_off[2], b_off[2];
#pragma unroll
    for (int mt = 0; mt < 2; mt++) {
        int row = warp_m * 32 + mt * 16 + (lane & 15);
        a_off[mt] = (uint32_t)(row * NSTR + (lane >> 4) * 8) * 2;
    }
#pragma unroll
    for (int np = 0; np < 2; np++) {
        int row = warp_n * 32 + np * 16 + (lane >> 4) * 8 + (lane & 7);
        b_off[np] = (uint32_t)(row * NSTR + ((lane >> 3) & 1) * 8) * 2;
    }

    float acc[2][4][4];
#pragma unroll
    for (int i = 0; i < 2; i++)
#pragma unroll
        for (int j = 0; j < 4; j++)
#pragma unroll
            for (int k = 0; k < 4; k++) acc[i][j][k] = 0.f;

    {
        const __nv_bfloat16* Ap = As[0] + (size_t)(ti * 64 + lr) * CH + lsp * 8;
        const __nv_bfloat16* Bp = Bs[0] + (size_t)(tj * 64 + lr) * CH + lsp * 8;
#pragma unroll
        for (int s4 = 0; s4 < 4; s4++) {
            CP_ASYNC16(dA + s4 * 16, Ap + s4 * 8);
            CP_ASYNC16(dB + s4 * 16, Bp + s4 * 8);
        }
        CP_COMMIT();
    }

    for (int c = 0; c < 12; c++) {
        int s = c & 1;
        if (c + 1 < 12) {
            int t1 = (c + 1) >> 2, kk1 = ((c + 1) & 3) * 64;
            int sn = (c + 1) & 1;
            const __nv_bfloat16* Ap = As[t1] + (size_t)(ti * 64 + lr) * CH + kk1 + lsp * 8;
            const __nv_bfloat16* Bp = Bs[t1] + (size_t)(tj * 64 + lr) * CH + kk1 + lsp * 8;
#pragma unroll
            for (int s4 = 0; s4 < 4; s4++) {
                CP_ASYNC16(dA + sn * stage + s4 * 16, Ap + s4 * 8);
                CP_ASYNC16(dB + sn * stage + s4 * 16, Bp + s4 * 8);
            }
        }
        CP_COMMIT();
        CP_WAIT1();
        __syncthreads();

        uint32_t bA = sA0 + s * stage, bB = sB0 + s * stage;
#pragma unroll
        for (int kh = 0; kh < 4; kh++) {
            uint32_t af[2][4], bfr[2][4];
#pragma unroll
            for (int mt = 0; mt < 2; mt++) ldm_x4(af[mt], bA + a_off[mt] + kh * 32);
#pragma unroll
            for (int np = 0; np < 2; np++) ldm_x4(bfr[np], bB + b_off[np] + kh * 32);
#pragma unroll
            for (int mt = 0; mt < 2; mt++)
#pragma unroll
                for (int nt = 0; nt < 4; nt++)
                    mma_bf16(acc[mt][nt], af[mt], &bfr[nt >> 1][(nt & 1) * 2]);
        }
        __syncthreads();
    }

    int grp = lane >> 2, qp = lane & 3;
#pragma unroll
    for (int mt = 0; mt < 2; mt++)
#pragma unroll
        for (int half = 0; half < 2; half++) {
            int row = ti * 64 + warp_m * 32 + mt * 16 + grp + half * 8;
#pragma unroll
            for (int nt = 0; nt < 4; nt++) {
                int col = tj * 64 + warp_n * 32 + nt * 8 + qp * 2;
                float v0 = acc[mt][nt][half * 2];
                float v1 = acc[mt][nt][half * 2 + 1];
                if (tEpi) {
                    v0 = ((row == col) ? 1.5f : 0.f) - 0.5f * v0;
                    v1 = ((row == col + 1) ? 1.5f : 0.f) - 0.5f * v1;
                }
                __nv_bfloat16 h0 = __float2bfloat16(v0);
                __nv_bfloat16 h1 = __float2bfloat16(v1);
                __nv_bfloat162 hv, lv;
                hv.x = h0; hv.y = h1;
                lv.x = __float2bfloat16(v0 - __bfloat162float(h0));
                lv.y = __float2bfloat16(v1 - __bfloat162float(h1));
                size_t o = boff + (size_t)row * CH + col;
                *(__nv_bfloat162*)(Ch + o) = hv;
                *(__nv_bfloat162*)(Cl + o) = lv;
                if (Cf) *(float2*)(Cf + o) = make_float2(v0, v1);
            }
        }
}

// T = 1.5I - 0.5 * Z@Y
__global__ void __launch_bounds__(128) nsT_kernel(int cur) {
    ns_mm_body(g_Zh[cur], g_Zl[cur], g_Yh[cur], g_Yl[cur], g_Th, g_Tl, nullptr, true);
}
// z=0: Ynew = Y@T ; z=1: Znew = Z@T
__global__ void __launch_bounds__(128) nsYZ_kernel(int cur) {
    int z = blockIdx.z;
    const __nv_bfloat16* Ah = z ? g_Zh[cur] : g_Yh[cur];
    const __nv_bfloat16* Al = z ? g_Zl[cur] : g_Yl[cur];
    __nv_bfloat16* Ch = z ? g_Zh[cur ^ 1] : g_Yh[cur ^ 1];
    __nv_bfloat16* Cl = z ? g_Zl[cur ^ 1] : g_Yl[cur ^ 1];
    ns_mm_body(Ah, Al, g_Th, g_Tl, Ch, Cl, nullptr, false);
}
// final iteration: only Z is needed; emit fp32 Z for the rowmean
__global__ void __launch_bounds__(128) nsZlast_kernel(int cur) {
    ns_mm_body(g_Zh[cur], g_Zl[cur], g_Th, g_Tl,
               g_Zh[cur ^ 1], g_Zl[cur ^ 1], g_Zf, false);
}

// ---------------- fused rowmean(Z)/sqrt(normA) + SE MLP + sigmoid ----------------
__global__ void __launch_bounds__(256) rowmean_se_kernel(
    const float* __restrict__ w1, const float* __restrict__ b1,
    const float* __restrict__ w2, const float* __restrict__ b2) {
    int b = blockIdx.x, c = threadIdx.x;
    __shared__ float ys[CH];
    __shared__ float hs[32];
    const float4* row = (const float4*)(g_Zf + ((size_t)b * CH + c) * CH);
    float s = 0.f;
#pragma unroll 8
    for (int d = 0; d < CH / 4; d++) {
        float4 v = row[d];
        s += v.x + v.y + v.z + v.w;
    }
    ys[c] = s * (1.f / CH) * g_rs[b];
    __syncthreads();
    if (c < 32) {
        float h = b1[c];
        const float* w = w1 + c * CH;
#pragma unroll 8
        for (int j = 0; j < CH; j++) h = fmaf(ys[j], w[j], h);
        hs[c] = fmaxf(h, 0.f);
    }
    __syncthreads();
    float g = b2[c];
    const float* w = w2 + c * 32;
#pragma unroll
    for (int j = 0; j < 32; j++) g = fmaf(hs[j], w[j], g);
    g_gate[b * CH + c] = 1.f / (1.f + expf(-g));
}

// ---------------- out = x * gate[b,c] ----------------
__global__ void __launch_bounds__(256) scale_kernel(const float* __restrict__ x,
                                                    float* __restrict__ out) {
    const float4* xi = (const float4*)x;
    float4* oo = (float4*)out;
    const size_t total = (size_t)BATCH * CH * MSP / 4;
    for (size_t i = (size_t)blockIdx.x * blockDim.x + threadIdx.x; i < total;
         i += (size_t)gridDim.x * blockDim.x) {
        float g = g_gate[i >> 12];
        float4 v = xi[i];
        v.x *= g; v.y *= g; v.z *= g; v.w *= g;
        oo[i] = v;
    }
}

// ---------------- launch ----------------
extern "C" void kernel_launch(void* const* d_in, const int* in_sizes, int n_in,
                              void* d_out, int out_size) {
    const float* x = (const float*)d_in[0];
    const float* w1 = (const float*)d_in[1];
    const float* b1 = (const float*)d_in[2];
    const float* w2 = (const float*)d_in[3];
    const float* b2 = (const float*)d_in[4];
    float* out = (float*)d_out;

    convert_kernel<<<BATCH * CH, 256>>>(x);
    gram_hmma_kernel<<<dim3(7, KSG, BATCH), 256>>>();
    cov_reduce_kernel<<<dim3(256, BATCH), 256>>>();
    init_frob_kernel<<<dim3(256, BATCH), 256>>>();

    int cur = 0;
    for (int it = 0; it < 4; it++) {
        nsT_kernel<<<dim3(16, BATCH), 128>>>(cur);
        nsYZ_kernel<<<dim3(16, BATCH, 2), 128>>>(cur);
        cur ^= 1;
    }
    nsT_kernel<<<dim3(16, BATCH), 128>>>(cur);
    nsZlast_kernel<<<dim3(16, BATCH), 128>>>(cur);

    rowmean_se_kernel<<<BATCH, 256>>>(w1, b1, w2, b2);
    scale_kernel<<<8192, 256>>>(x, out);
}

// round 10
// speedup vs baseline: 1.3757x; 1.2163x over previous
#include <cuda_runtime.h>
#include <cuda_bf16.h>
#include <cstdint>
#include <math.h>

#define BATCH 8
#define CH 256
#define MSP 16384          // H*W
#define MAT (CH * CH)      // 65536
#define KSG 16             // gram K-split: 3*16*8=384 CTAs
#define KLOC (MSP / KSG)   // 1024
#define KCH 32             // gram k per pipeline chunk
#define NCH (KLOC / KCH)   // 32
#define ASTR 40            // gram smem row stride (bf16): conflict-free ldmatrix
#define NSTR 72            // NS smem row stride (bf16)
#define NS_STAGE (64 * NSTR)

// ---------------- device scratch (no allocations allowed) ----------------
__device__ __nv_bfloat16 g_hi[(size_t)BATCH * CH * MSP];
__device__ float g_g1p[KSG][BATCH * MAT];
__device__ float g_cov[BATCH * MAT];
__device__ float g_mu[BATCH * CH];
__device__ float g_fpart[BATCH][256];
__device__ float g_rs[BATCH];
__device__ __nv_bfloat16 g_Yh[2][BATCH * MAT];
__device__ __nv_bfloat16 g_Yl[2][BATCH * MAT];
__device__ __nv_bfloat16 g_Zh[2][BATCH * MAT];
__device__ __nv_bfloat16 g_Zl[2][BATCH * MAT];
__device__ __nv_bfloat16 g_Th[BATCH * MAT];
__device__ __nv_bfloat16 g_Tl[BATCH * MAT];
__device__ float g_Zf[BATCH * MAT];
__device__ float g_gate[BATCH * CH];

// ---------------- PTX helpers (baseline ISA only) ----------------
__device__ __forceinline__ uint32_t smem_u32(const void* p) {
    uint32_t a;
    asm("{ .reg .u64 t; cvta.to.shared.u64 t, %1; cvt.u32.u64 %0, t; }"
        : "=r"(a) : "l"(p));
    return a;
}
#define CP_ASYNC16(dst, src) \
    asm volatile("cp.async.cg.shared.global [%0], [%1], 16;" :: "r"(dst), "l"(src))
#define CP_COMMIT() asm volatile("cp.async.commit_group;" ::: "memory")
#define CP_WAIT1() asm volatile("cp.async.wait_group 1;" ::: "memory")

__device__ __forceinline__ void ldm_x4(uint32_t* r, uint32_t addr) {
    asm volatile("ldmatrix.sync.aligned.m8n8.x4.shared.b16 {%0,%1,%2,%3}, [%4];"
                 : "=r"(r[0]), "=r"(r[1]), "=r"(r[2]), "=r"(r[3]) : "r"(addr));
}
__device__ __forceinline__ void ldm_x2(uint32_t* r, uint32_t addr) {
    asm volatile("ldmatrix.sync.aligned.m8n8.x2.shared.b16 {%0,%1}, [%2];"
                 : "=r"(r[0]), "=r"(r[1]) : "r"(addr));
}
__device__ __forceinline__ void mma_bf16(float* c, const uint32_t* a, const uint32_t* b) {
    asm volatile(
        "mma.sync.aligned.m16n8k16.row.col.f32.bf16.bf16.f32 "
        "{%0,%1,%2,%3}, {%4,%5,%6,%7}, {%8,%9}, {%0,%1,%2,%3};"
        : "+f"(c[0]), "+f"(c[1]), "+f"(c[2]), "+f"(c[3])
        : "r"(a[0]), "r"(a[1]), "r"(a[2]), "r"(a[3]), "r"(b[0]), "r"(b[1]));
}

// ---------------- helpers ----------------
__device__ __forceinline__ float blockReduceSum256(float v) {
    __shared__ float sh[8];
    int lane = threadIdx.x & 31, w = threadIdx.x >> 5;
#pragma unroll
    for (int o = 16; o; o >>= 1) v += __shfl_down_sync(0xffffffffu, v, o);
    if (lane == 0) sh[w] = v;
    __syncthreads();
    if (threadIdx.x < 32) {
        v = (threadIdx.x < 8) ? sh[threadIdx.x] : 0.f;
#pragma unroll
        for (int o = 4; o; o >>= 1) v += __shfl_down_sync(0xffffffffu, v, o);
    }
    return v;  // valid in thread 0
}

// ---------------- fused: bf16 cast + per-(b,c) spatial mean ----------------
__global__ void __launch_bounds__(256) convert_kernel(const float* __restrict__ x) {
    int bc = blockIdx.x;  // 0..2047
    const float4* p = (const float4*)(x + (size_t)bc * MSP);
    __nv_bfloat162* hi2 = (__nv_bfloat162*)g_hi + (size_t)bc * (MSP / 2);
    float s = 0.f;
    for (int t = threadIdx.x; t < MSP / 4; t += 256) {
        float4 v = p[t];
        s += v.x + v.y + v.z + v.w;
        __nv_bfloat162 a, b;
        a.x = __float2bfloat16(v.x); a.y = __float2bfloat16(v.y);
        b.x = __float2bfloat16(v.z); b.y = __float2bfloat16(v.w);
        hi2[t * 2] = a; hi2[t * 2 + 1] = b;
    }
    s = blockReduceSum256(s);
    if (threadIdx.x == 0) g_mu[bc] = s * (1.f / MSP);
}

// ---------------- Gram via HMMA: G1 = hi.hi^T upper tiles, KSG=16 --------------
__global__ void __launch_bounds__(256, 2) gram_hmma_kernel() {
    __shared__ __nv_bfloat16 sA[2][128 * ASTR];
    __shared__ __nv_bfloat16 sB[2][128 * ASTR];

    int tid = threadIdx.x, wid = tid >> 5, lane = tid & 31;
    int t = blockIdx.x, ks = blockIdx.y, b = blockIdx.z;
    int ti = (t == 2) ? 1 : 0;
    int tj = (t == 0) ? 0 : 1;

    const __nv_bfloat16* Ag =
        g_hi + ((size_t)b * CH + (size_t)ti * 128) * MSP + (size_t)ks * KLOC;
    const __nv_bfloat16* Bg =
        g_hi + ((size_t)b * CH + (size_t)tj * 128) * MSP + (size_t)ks * KLOC;

    uint32_t sA0 = smem_u32(&sA[0][0]);
    uint32_t sB0 = smem_u32(&sB[0][0]);
    const uint32_t stageA = 128 * ASTR * 2;
    const uint32_t stageB = 128 * ASTR * 2;

    int lr = tid >> 1;
    int lf = (tid & 1) * 2;
    uint32_t dstA = sA0 + (uint32_t)(lr * ASTR + lf * 8) * 2;
    uint32_t dstB = sB0 + (uint32_t)(lr * ASTR + lf * 8) * 2;

    int warp_m = wid >> 2, warp_n = wid & 3;
    uint32_t a_off[4], b_off[4];
#pragma unroll
    for (int mt = 0; mt < 4; mt++) {
        int row = warp_m * 64 + mt * 16 + (lane & 15);
        a_off[mt] = (uint32_t)(row * ASTR + (lane >> 4) * 8) * 2;
    }
#pragma unroll
    for (int nt = 0; nt < 4; nt++) {
        int l2 = lane & 15;
        int row = warp_n * 32 + nt * 8 + (l2 & 7);
        b_off[nt] = (uint32_t)(row * ASTR + (l2 >> 3) * 8) * 2;
    }

    float acc[4][4][4];
#pragma unroll
    for (int i = 0; i < 4; i++)
#pragma unroll
        for (int j = 0; j < 4; j++)
#pragma unroll
            for (int k = 0; k < 4; k++) acc[i][j][k] = 0.f;

    {
        const __nv_bfloat16* Ap = Ag + (size_t)lr * MSP + lf * 8;
        const __nv_bfloat16* Bp = Bg + (size_t)lr * MSP + lf * 8;
        CP_ASYNC16(dstA, Ap); CP_ASYNC16(dstA + 16, Ap + 8);
        CP_ASYNC16(dstB, Bp); CP_ASYNC16(dstB + 16, Bp + 8);
        CP_COMMIT();
    }

    for (int c = 0; c < NCH; c++) {
        int s = c & 1;
        if (c + 1 < NCH) {
            int sn = (c + 1) & 1;
            const __nv_bfloat16* Ap = Ag + (size_t)lr * MSP + (c + 1) * KCH + lf * 8;
            const __nv_bfloat16* Bp = Bg + (size_t)lr * MSP + (c + 1) * KCH + lf * 8;
            CP_ASYNC16(dstA + sn * stageA, Ap); CP_ASYNC16(dstA + sn * stageA + 16, Ap + 8);
            CP_ASYNC16(dstB + sn * stageB, Bp); CP_ASYNC16(dstB + sn * stageB + 16, Bp + 8);
        }
        CP_COMMIT();
        CP_WAIT1();
        __syncthreads();

        uint32_t baseA = sA0 + s * stageA;
        uint32_t baseB = sB0 + s * stageB;
#pragma unroll
        for (int kh = 0; kh < 2; kh++) {
            uint32_t af[4][4], bf[4][2];
#pragma unroll
            for (int mt = 0; mt < 4; mt++) ldm_x4(af[mt], baseA + a_off[mt] + kh * 32);
#pragma unroll
            for (int nt = 0; nt < 4; nt++) ldm_x2(bf[nt], baseB + b_off[nt] + kh * 32);
#pragma unroll
            for (int mt = 0; mt < 4; mt++)
#pragma unroll
                for (int nt = 0; nt < 4; nt++) mma_bf16(acc[mt][nt], af[mt], bf[nt]);
        }
        __syncthreads();
    }

    float* dst = g_g1p[ks] + (size_t)b * MAT;
    int grp = lane >> 2, qp = lane & 3;
#pragma unroll
    for (int mt = 0; mt < 4; mt++) {
        int row0 = ti * 128 + warp_m * 64 + mt * 16;
#pragma unroll
        for (int nt = 0; nt < 4; nt++) {
            int col0 = tj * 128 + warp_n * 32 + nt * 8 + qp * 2;
            float2 v0 = make_float2(acc[mt][nt][0], acc[mt][nt][1]);
            float2 v1 = make_float2(acc[mt][nt][2], acc[mt][nt][3]);
            *(float2*)(dst + (size_t)(row0 + grp) * CH + col0) = v0;
            *(float2*)(dst + (size_t)(row0 + grp + 8) * CH + col0) = v1;
        }
    }
}

// ---------------- reduce partials -> centered covariance (+frobenius partials) ----
__global__ void __launch_bounds__(256) cov_reduce_kernel() {
    int b = blockIdx.y;
    int idx = blockIdx.x * 256 + threadIdx.x;
    int i = idx >> 8, j = idx & 255;
    int si = (i <= j) ? i : j;
    int sj = (i <= j) ? j : i;
    float s = 0.f;
#pragma unroll
    for (int ks = 0; ks < KSG; ks++)
        s += g_g1p[ks][(size_t)b * MAT + si * CH + sj];
    float v = s * (1.f / MSP) - g_mu[b * CH + i] * g_mu[b * CH + j];
    g_cov[(size_t)b * MAT + idx] = v;
    float sq = blockReduceSum256(v * v);
    if (threadIdx.x == 0) g_fpart[b][blockIdx.x] = sq;
}

// ---------------- fused frobenius finalize + init Y0 = cov/normA, Z0 = I --------
__global__ void __launch_bounds__(256) init_frob_kernel() {
    __shared__ float tot;
    int b = blockIdx.y;
    float s = blockReduceSum256(g_fpart[b][threadIdx.x]);
    if (threadIdx.x == 0) tot = s;
    __syncthreads();
    float fs = tot;
    float n = sqrtf(fs);
    float inv = 1.f / n;
    if (blockIdx.x == 0 && threadIdx.x == 0) g_rs[b] = rsqrtf(n);

    int idx = blockIdx.x * 256 + threadIdx.x;
    size_t o = (size_t)b * MAT + idx;
    float v = g_cov[o] * inv;
    __nv_bfloat16 h = __float2bfloat16(v);
    g_Yh[0][o] = h;
    g_Yl[0][o] = __float2bfloat16(v - __bfloat162float(h));
    int i = idx >> 8, j = idx & 255;
    g_Zh[0][o] = __float2bfloat16((i == j) ? 1.f : 0.f);
    g_Zl[0][o] = __float2bfloat16(0.f);
}

// ---------------- NS matmul via HMMA: C = A.B (A,B symmetric, split bf16) ------
__device__ __forceinline__ void ns_mm_body(
    const __nv_bfloat16* __restrict__ Ah, const __nv_bfloat16* __restrict__ Al,
    const __nv_bfloat16* __restrict__ Bh, const __nv_bfloat16* __restrict__ Bl,
    __nv_bfloat16* __restrict__ Ch, __nv_bfloat16* __restrict__ Cl,
    float* __restrict__ Cf, bool tEpi) {
    __shared__ __nv_bfloat16 sA[2][NS_STAGE];
    __shared__ __nv_bfloat16 sB[2][NS_STAGE];
    int bb = blockIdx.y;
    size_t boff = (size_t)bb * MAT;
    int ti = blockIdx.x >> 2, tj = blockIdx.x & 3;
    int tid = threadIdx.x, wid = tid >> 5, lane = tid & 31;
    int warp_m = wid & 1, warp_n = wid >> 1;

    const __nv_bfloat16* As[3] = {Ah + boff, Ah + boff, Al + boff};
    const __nv_bfloat16* Bs[3] = {Bh + boff, Bl + boff, Bh + boff};

    uint32_t sA0 = smem_u32(&sA[0][0]), sB0 = smem_u32(&sB[0][0]);
    const uint32_t stage = NS_STAGE * 2;

    int lr = tid >> 1;
    int lsp = (tid & 1) * 4;
    uint32_t dA = sA0 + (uint32_t)(lr * NSTR + lsp * 8) * 2;
    uint32_t dB = sB0 + (uint32_t)(lr * NSTR + lsp * 8) * 2;

    uint32_t a_off[2], b_off[2];
#pragma unroll
    for (int mt = 0; mt < 2; mt++) {
        int row = warp_m * 32 + mt * 16 + (lane & 15);
        a_off[mt] = (uint32_t)(row * NSTR + (lane >> 4) * 8) * 2;
    }
#pragma unroll
    for (int np = 0; np < 2; np++) {
        int row = warp_n * 32 + np * 16 + (lane >> 4) * 8 + (lane & 7);
        b_off[np] = (uint32_t)(row * NSTR + ((lane >> 3) & 1) * 8) * 2;
    }

    float acc[2][4][4];
#pragma unroll
    for (int i = 0; i < 2; i++)
#pragma unroll
        for (int j = 0; j < 4; j++)
#pragma unroll
            for (int k = 0; k < 4; k++) acc[i][j][k] = 0.f;

    {
        const __nv_bfloat16* Ap = As[0] + (size_t)(ti * 64 + lr) * CH + lsp * 8;
        const __nv_bfloat16* Bp = Bs[0] + (size_t)(tj * 64 + lr) * CH + lsp * 8;
#pragma unroll
        for (int s4 = 0; s4 < 4; s4++) {
            CP_ASYNC16(dA + s4 * 16, Ap + s4 * 8);
            CP_ASYNC16(dB + s4 * 16, Bp + s4 * 8);
        }
        CP_COMMIT();
    }

    for (int c = 0; c < 12; c++) {
        int s = c & 1;
        if (c + 1 < 12) {
            int t1 = (c + 1) >> 2, kk1 = ((c + 1) & 3) * 64;
            int sn = (c + 1) & 1;
            const __nv_bfloat16* Ap = As[t1] + (size_t)(ti * 64 + lr) * CH + kk1 + lsp * 8;
            const __nv_bfloat16* Bp = Bs[t1] + (size_t)(tj * 64 + lr) * CH + kk1 + lsp * 8;
#pragma unroll
            for (int s4 = 0; s4 < 4; s4++) {
                CP_ASYNC16(dA + sn * stage + s4 * 16, Ap + s4 * 8);
                CP_ASYNC16(dB + sn * stage + s4 * 16, Bp + s4 * 8);
            }
        }
        CP_COMMIT();
        CP_WAIT1();
        __syncthreads();

        uint32_t bA = sA0 + s * stage, bB = sB0 + s * stage;
#pragma unroll
        for (int kh = 0; kh < 4; kh++) {
            uint32_t af[2][4], bfr[2][4];
#pragma unroll
            for (int mt = 0; mt < 2; mt++) ldm_x4(af[mt], bA + a_off[mt] + kh * 32);
#pragma unroll
            for (int np = 0; np < 2; np++) ldm_x4(bfr[np], bB + b_off[np] + kh * 32);
#pragma unroll
            for (int mt = 0; mt < 2; mt++)
#pragma unroll
                for (int nt = 0; nt < 4; nt++)
                    mma_bf16(acc[mt][nt], af[mt], &bfr[nt >> 1][(nt & 1) * 2]);
        }
        __syncthreads();
    }

    int grp = lane >> 2, qp = lane & 3;
#pragma unroll
    for (int mt = 0; mt < 2; mt++)
#pragma unroll
        for (int half = 0; half < 2; half++) {
            int row = ti * 64 + warp_m * 32 + mt * 16 + grp + half * 8;
#pragma unroll
            for (int nt = 0; nt < 4; nt++) {
                int col = tj * 64 + warp_n * 32 + nt * 8 + qp * 2;
                float v0 = acc[mt][nt][half * 2];
                float v1 = acc[mt][nt][half * 2 + 1];
                if (tEpi) {
                    v0 = ((row == col) ? 1.5f : 0.f) - 0.5f * v0;
                    v1 = ((row == col + 1) ? 1.5f : 0.f) - 0.5f * v1;
                }
                __nv_bfloat16 h0 = __float2bfloat16(v0);
                __nv_bfloat16 h1 = __float2bfloat16(v1);
                __nv_bfloat162 hv, lv;
                hv.x = h0; hv.y = h1;
                lv.x = __float2bfloat16(v0 - __bfloat162float(h0));
                lv.y = __float2bfloat16(v1 - __bfloat162float(h1));
                size_t o = boff + (size_t)row * CH + col;
                *(__nv_bfloat162*)(Ch + o) = hv;
                *(__nv_bfloat162*)(Cl + o) = lv;
                if (Cf) *(float2*)(Cf + o) = make_float2(v0, v1);
            }
        }
}

// T = 1.5I - 0.5 * Z@Y
__global__ void __launch_bounds__(128) nsT_kernel(int cur) {
    ns_mm_body(g_Zh[cur], g_Zl[cur], g_Yh[cur], g_Yl[cur], g_Th, g_Tl, nullptr, true);
}
// z=0: Ynew = Y@T ; z=1: Znew = Z@T
__global__ void __launch_bounds__(128) nsYZ_kernel(int cur) {
    int z = blockIdx.z;
    const __nv_bfloat16* Ah = z ? g_Zh[cur] : g_Yh[cur];
    const __nv_bfloat16* Al = z ? g_Zl[cur] : g_Yl[cur];
    __nv_bfloat16* Ch = z ? g_Zh[cur ^ 1] : g_Yh[cur ^ 1];
    __nv_bfloat16* Cl = z ? g_Zl[cur ^ 1] : g_Yl[cur ^ 1];
    ns_mm_body(Ah, Al, g_Th, g_Tl, Ch, Cl, nullptr, false);
}
// final iteration: only Z is needed; emit fp32 Z for the rowmean
__global__ void __launch_bounds__(128) nsZlast_kernel(int cur) {
    ns_mm_body(g_Zh[cur], g_Zl[cur], g_Th, g_Tl,
               g_Zh[cur ^ 1], g_Zl[cur ^ 1], g_Zf, false);
}

// ---------------- fused rowmean(Z)/sqrt(normA) + SE MLP + sigmoid ----------------
__global__ void __launch_bounds__(256) rowmean_se_kernel(
    const float* __restrict__ w1, const float* __restrict__ b1,
    const float* __restrict__ w2, const float* __restrict__ b2) {
    int b = blockIdx.x, c = threadIdx.x;
    __shared__ float ys[CH];
    __shared__ float hs[32];
    const float4* row = (const float4*)(g_Zf + ((size_t)b * CH + c) * CH);
    float s = 0.f;
#pragma unroll 8
    for (int d = 0; d < CH / 4; d++) {
        float4 v = row[d];
        s += v.x + v.y + v.z + v.w;
    }
    ys[c] = s * (1.f / CH) * g_rs[b];
    __syncthreads();
    if (c < 32) {
        float h = b1[c];
        const float* w = w1 + c * CH;
#pragma unroll 8
        for (int j = 0; j < CH; j++) h = fmaf(ys[j], w[j], h);
        hs[c] = fmaxf(h, 0.f);
    }
    __syncthreads();
    float g = b2[c];
    const float* w = w2 + c * 32;
#pragma unroll
    for (int j = 0; j < 32; j++) g = fmaf(hs[j], w[j], g);
    g_gate[b * CH + c] = 1.f / (1.f + expf(-g));
}

// ---------------- out = x * gate[b,c] ----------------
__global__ void __launch_bounds__(256) scale_kernel(const float* __restrict__ x,
                                                    float* __restrict__ out) {
    const float4* xi = (const float4*)x;
    float4* oo = (float4*)out;
    const size_t total = (size_t)BATCH * CH * MSP / 4;
    for (size_t i = (size_t)blockIdx.x * blockDim.x + threadIdx.x; i < total;
         i += (size_t)gridDim.x * blockDim.x) {
        float g = g_gate[i >> 12];
        float4 v = xi[i];
        v.x *= g; v.y *= g; v.z *= g; v.w *= g;
        oo[i] = v;
    }
}

// ---------------- launch ----------------
extern "C" void kernel_launch(void* const* d_in, const int* in_sizes, int n_in,
                              void* d_out, int out_size) {
    const float* x = (const float*)d_in[0];
    const float* w1 = (const float*)d_in[1];
    const float* b1 = (const float*)d_in[2];
    const float* w2 = (const float*)d_in[3];
    const float* b2 = (const float*)d_in[4];
    float* out = (float*)d_out;

    convert_kernel<<<BATCH * CH, 256>>>(x);
    gram_hmma_kernel<<<dim3(3, KSG, BATCH), 256>>>();
    cov_reduce_kernel<<<dim3(256, BATCH), 256>>>();
    init_frob_kernel<<<dim3(256, BATCH), 256>>>();

    int cur = 0;
    for (int it = 0; it < 4; it++) {
        nsT_kernel<<<dim3(16, BATCH), 128>>>(cur);
        nsYZ_kernel<<<dim3(16, BATCH, 2), 128>>>(cur);
        cur ^= 1;
    }
    nsT_kernel<<<dim3(16, BATCH), 128>>>(cur);
    nsZlast_kernel<<<dim3(16, BATCH), 128>>>(cur);

    rowmean_se_kernel<<<BATCH, 256>>>(w1, b1, w2, b2);
    scale_kernel<<<8192, 256>>>(x, out);
}

// round 16
// speedup vs baseline: 1.7338x; 1.2604x over previous
#include <cuda_runtime.h>
#include <cuda_bf16.h>
#include <cstdint>
#include <math.h>

#define BATCH 8
#define CH 256
#define MSP 16384          // H*W
#define MAT (CH * CH)      // 65536
#define KSG 16             // gram K-split: 3*16*8=384 CTAs
#define KLOC (MSP / KSG)   // 1024
#define KCH 32             // gram k per pipeline chunk
#define NCH (KLOC / KCH)   // 32
#define ASTR 40            // gram smem row stride (bf16): conflict-free ldmatrix
#define NSTR 72            // NS smem row stride (bf16)
#define NS_STAGE (64 * NSTR)

// ---------------- device scratch (no allocations allowed) ----------------
__device__ __nv_bfloat16 g_hi[(size_t)BATCH * CH * MSP];
__device__ float g_g1p[KSG][BATCH * MAT];
__device__ float g_cov[BATCH * MAT];
__device__ float g_mu[BATCH * CH];
__device__ float g_fpart[BATCH][256];
__device__ float g_rs[BATCH];
__device__ __nv_bfloat16 g_Yh[2][BATCH * MAT];
__device__ __nv_bfloat16 g_Zh[2][BATCH * MAT];
__device__ __nv_bfloat16 g_Th[BATCH * MAT];
__device__ float g_Zf[BATCH * MAT];
__device__ float g_gate[BATCH * CH];

// ---------------- PTX helpers (baseline ISA only) ----------------
__device__ __forceinline__ uint32_t smem_u32(const void* p) {
    uint32_t a;
    asm("{ .reg .u64 t; cvta.to.shared.u64 t, %1; cvt.u32.u64 %0, t; }"
        : "=r"(a) : "l"(p));
    return a;
}
#define CP_ASYNC16(dst, src) \
    asm volatile("cp.async.cg.shared.global [%0], [%1], 16;" :: "r"(dst), "l"(src))
#define CP_COMMIT() asm volatile("cp.async.commit_group;" ::: "memory")
#define CP_WAIT1() asm volatile("cp.async.wait_group 1;" ::: "memory")

__device__ __forceinline__ void ldm_x4(uint32_t* r, uint32_t addr) {
    asm volatile("ldmatrix.sync.aligned.m8n8.x4.shared.b16 {%0,%1,%2,%3}, [%4];"
                 : "=r"(r[0]), "=r"(r[1]), "=r"(r[2]), "=r"(r[3]) : "r"(addr));
}
__device__ __forceinline__ void ldm_x2(uint32_t* r, uint32_t addr) {
    asm volatile("ldmatrix.sync.aligned.m8n8.x2.shared.b16 {%0,%1}, [%2];"
                 : "=r"(r[0]), "=r"(r[1]) : "r"(addr));
}
__device__ __forceinline__ void mma_bf16(float* c, const uint32_t* a, const uint32_t* b) {
    asm volatile(
        "mma.sync.aligned.m16n8k16.row.col.f32.bf16.bf16.f32 "
        "{%0,%1,%2,%3}, {%4,%5,%6,%7}, {%8,%9}, {%0,%1,%2,%3};"
        : "+f"(c[0]), "+f"(c[1]), "+f"(c[2]), "+f"(c[3])
        : "r"(a[0]), "r"(a[1]), "r"(a[2]), "r"(a[3]), "r"(b[0]), "r"(b[1]));
}

// ---------------- helpers ----------------
__device__ __forceinline__ float blockReduceSum256(float v) {
    __shared__ float sh[8];
    int lane = threadIdx.x & 31, w = threadIdx.x >> 5;
#pragma unroll
    for (int o = 16; o; o >>= 1) v += __shfl_down_sync(0xffffffffu, v, o);
    if (lane == 0) sh[w] = v;
    __syncthreads();
    if (threadIdx.x < 32) {
        v = (threadIdx.x < 8) ? sh[threadIdx.x] : 0.f;
#pragma unroll
        for (int o = 4; o; o >>= 1) v += __shfl_down_sync(0xffffffffu, v, o);
    }
    return v;  // valid in thread 0
}

// ---------------- fused: bf16 cast + per-(b,c) spatial mean ----------------
__global__ void __launch_bounds__(256) convert_kernel(const float* __restrict__ x) {
    int bc = blockIdx.x;  // 0..2047
    const float4* p = (const float4*)(x + (size_t)bc * MSP);
    __nv_bfloat162* hi2 = (__nv_bfloat162*)g_hi + (size_t)bc * (MSP / 2);
    float s = 0.f;
    for (int t = threadIdx.x; t < MSP / 4; t += 256) {
        float4 v = p[t];
        s += v.x + v.y + v.z + v.w;
        __nv_bfloat162 a, b;
        a.x = __float2bfloat16(v.x); a.y = __float2bfloat16(v.y);
        b.x = __float2bfloat16(v.z); b.y = __float2bfloat16(v.w);
        hi2[t * 2] = a; hi2[t * 2 + 1] = b;
    }
    s = blockReduceSum256(s);
    if (threadIdx.x == 0) g_mu[bc] = s * (1.f / MSP);
}

// ---------------- Gram via HMMA: G1 = hi.hi^T upper tiles, KSG=16 --------------
__global__ void __launch_bounds__(256, 2) gram_hmma_kernel() {
    __shared__ __nv_bfloat16 sA[2][128 * ASTR];
    __shared__ __nv_bfloat16 sB[2][128 * ASTR];

    int tid = threadIdx.x, wid = tid >> 5, lane = tid & 31;
    int t = blockIdx.x, ks = blockIdx.y, b = blockIdx.z;
    int ti = (t == 2) ? 1 : 0;
    int tj = (t == 0) ? 0 : 1;

    const __nv_bfloat16* Ag =
        g_hi + ((size_t)b * CH + (size_t)ti * 128) * MSP + (size_t)ks * KLOC;
    const __nv_bfloat16* Bg =
        g_hi + ((size_t)b * CH + (size_t)tj * 128) * MSP + (size_t)ks * KLOC;

    uint32_t sA0 = smem_u32(&sA[0][0]);
    uint32_t sB0 = smem_u32(&sB[0][0]);
    const uint32_t stageA = 128 * ASTR * 2;
    const uint32_t stageB = 128 * ASTR * 2;

    int lr = tid >> 1;
    int lf = (tid & 1) * 2;
    uint32_t dstA = sA0 + (uint32_t)(lr * ASTR + lf * 8) * 2;
    uint32_t dstB = sB0 + (uint32_t)(lr * ASTR + lf * 8) * 2;

    int warp_m = wid >> 2, warp_n = wid & 3;
    uint32_t a_off[4], b_off[4];
#pragma unroll
    for (int mt = 0; mt < 4; mt++) {
        int row = warp_m * 64 + mt * 16 + (lane & 15);
        a_off[mt] = (uint32_t)(row * ASTR + (lane >> 4) * 8) * 2;
    }
#pragma unroll
    for (int nt = 0; nt < 4; nt++) {
        int l2 = lane & 15;
        int row = warp_n * 32 + nt * 8 + (l2 & 7);
        b_off[nt] = (uint32_t)(row * ASTR + (l2 >> 3) * 8) * 2;
    }

    float acc[4][4][4];
#pragma unroll
    for (int i = 0; i < 4; i++)
#pragma unroll
        for (int j = 0; j < 4; j++)
#pragma unroll
            for (int k = 0; k < 4; k++) acc[i][j][k] = 0.f;

    {
        const __nv_bfloat16* Ap = Ag + (size_t)lr * MSP + lf * 8;
        const __nv_bfloat16* Bp = Bg + (size_t)lr * MSP + lf * 8;
        CP_ASYNC16(dstA, Ap); CP_ASYNC16(dstA + 16, Ap + 8);
        CP_ASYNC16(dstB, Bp); CP_ASYNC16(dstB + 16, Bp + 8);
        CP_COMMIT();
    }

    for (int c = 0; c < NCH; c++) {
        int s = c & 1;
        if (c + 1 < NCH) {
            int sn = (c + 1) & 1;
            const __nv_bfloat16* Ap = Ag + (size_t)lr * MSP + (c + 1) * KCH + lf * 8;
            const __nv_bfloat16* Bp = Bg + (size_t)lr * MSP + (c + 1) * KCH + lf * 8;
            CP_ASYNC16(dstA + sn * stageA, Ap); CP_ASYNC16(dstA + sn * stageA + 16, Ap + 8);
            CP_ASYNC16(dstB + sn * stageB, Bp); CP_ASYNC16(dstB + sn * stageB + 16, Bp + 8);
        }
        CP_COMMIT();
        CP_WAIT1();
        __syncthreads();

        uint32_t baseA = sA0 + s * stageA;
        uint32_t baseB = sB0 + s * stageB;
#pragma unroll
        for (int kh = 0; kh < 2; kh++) {
            uint32_t af[4][4], bf[4][2];
#pragma unroll
            for (int mt = 0; mt < 4; mt++) ldm_x4(af[mt], baseA + a_off[mt] + kh * 32);
#pragma unroll
            for (int nt = 0; nt < 4; nt++) ldm_x2(bf[nt], baseB + b_off[nt] + kh * 32);
#pragma unroll
            for (int mt = 0; mt < 4; mt++)
#pragma unroll
                for (int nt = 0; nt < 4; nt++) mma_bf16(acc[mt][nt], af[mt], bf[nt]);
        }
        __syncthreads();
    }

    float* dst = g_g1p[ks] + (size_t)b * MAT;
    int grp = lane >> 2, qp = lane & 3;
#pragma unroll
    for (int mt = 0; mt < 4; mt++) {
        int row0 = ti * 128 + warp_m * 64 + mt * 16;
#pragma unroll
        for (int nt = 0; nt < 4; nt++) {
            int col0 = tj * 128 + warp_n * 32 + nt * 8 + qp * 2;
            float2 v0 = make_float2(acc[mt][nt][0], acc[mt][nt][1]);
            float2 v1 = make_float2(acc[mt][nt][2], acc[mt][nt][3]);
            *(float2*)(dst + (size_t)(row0 + grp) * CH + col0) = v0;
            *(float2*)(dst + (size_t)(row0 + grp + 8) * CH + col0) = v1;
        }
    }
}

// ---------------- reduce partials -> centered covariance (+frobenius partials) ----
__global__ void __launch_bounds__(256) cov_reduce_kernel() {
    int b = blockIdx.y;
    int idx = blockIdx.x * 256 + threadIdx.x;
    int i = idx >> 8, j = idx & 255;
    int si = (i <= j) ? i : j;
    int sj = (i <= j) ? j : i;
    float s = 0.f;
#pragma unroll
    for (int ks = 0; ks < KSG; ks++)
        s += g_g1p[ks][(size_t)b * MAT + si * CH + sj];
    float v = s * (1.f / MSP) - g_mu[b * CH + i] * g_mu[b * CH + j];
    g_cov[(size_t)b * MAT + idx] = v;
    float sq = blockReduceSum256(v * v);
    if (threadIdx.x == 0) g_fpart[b][blockIdx.x] = sq;
}

// ---------------- fused frobenius finalize + init Y0 = cov/normA, Z0 = I --------
__global__ void __launch_bounds__(256) init_frob_kernel() {
    __shared__ float tot;
    int b = blockIdx.y;
    float s = blockReduceSum256(g_fpart[b][threadIdx.x]);
    if (threadIdx.x == 0) tot = s;
    __syncthreads();
    float fs = tot;
    float n = sqrtf(fs);
    float inv = 1.f / n;
    if (blockIdx.x == 0 && threadIdx.x == 0) g_rs[b] = rsqrtf(n);

    int idx = blockIdx.x * 256 + threadIdx.x;
    size_t o = (size_t)b * MAT + idx;
    float v = g_cov[o] * inv;
    g_Yh[0][o] = __float2bfloat16(v);
    int i = idx >> 8, j = idx & 255;
    g_Zh[0][o] = __float2bfloat16((i == j) ? 1.f : 0.f);
}

// ---------------- NS matmul via HMMA: C = A.B (A,B symmetric bf16) --------------
// 64x64 tile/CTA, 128 thr (4 warps, 2x2, 32x32 warp tiles), K=256 in 4 chunks
__device__ __forceinline__ void ns_mm_body(
    const __nv_bfloat16* __restrict__ A, const __nv_bfloat16* __restrict__ B,
    __nv_bfloat16* __restrict__ C, float* __restrict__ Cf, bool tEpi) {
    __shared__ __nv_bfloat16 sA[2][NS_STAGE];
    __shared__ __nv_bfloat16 sB[2][NS_STAGE];
    int bb = blockIdx.y;
    size_t boff = (size_t)bb * MAT;
    A += boff; B += boff;
    int ti = blockIdx.x >> 2, tj = blockIdx.x & 3;
    int tid = threadIdx.x, wid = tid >> 5, lane = tid & 31;
    int warp_m = wid & 1, warp_n = wid >> 1;

    uint32_t sA0 = smem_u32(&sA[0][0]), sB0 = smem_u32(&sB[0][0]);
    const uint32_t stage = NS_STAGE * 2;

    int lr = tid >> 1;
    int lsp = (tid & 1) * 4;
    uint32_t dA = sA0 + (uint32_t)(lr * NSTR + lsp * 8) * 2;
    uint32_t dB = sB0 + (uint32_t)(lr * NSTR + lsp * 8) * 2;
    const __nv_bfloat16* Arow = A + (size_t)(ti * 64 + lr) * CH + lsp * 8;
    const __nv_bfloat16* Brow = B + (size_t)(tj * 64 + lr) * CH + lsp * 8;

    uint32_t a_off[2], b_off[2];
#pragma unroll
    for (int mt = 0; mt < 2; mt++) {
        int row = warp_m * 32 + mt * 16 + (lane & 15);
        a_off[mt] = (uint32_t)(row * NSTR + (lane >> 4) * 8) * 2;
    }
#pragma unroll
    for (int np = 0; np < 2; np++) {
        int row = warp_n * 32 + np * 16 + (lane >> 4) * 8 + (lane & 7);
        b_off[np] = (uint32_t)(row * NSTR + ((lane >> 3) & 1) * 8) * 2;
    }

    float acc[2][4][4];
#pragma unroll
    for (int i = 0; i < 2; i++)
#pragma unroll
        for (int j = 0; j < 4; j++)
#pragma unroll
            for (int k = 0; k < 4; k++) acc[i][j][k] = 0.f;

    {
#pragma unroll
        for (int s4 = 0; s4 < 4; s4++) {
            CP_ASYNC16(dA + s4 * 16, Arow + s4 * 8);
            CP_ASYNC16(dB + s4 * 16, Brow + s4 * 8);
        }
        CP_COMMIT();
    }

    for (int c = 0; c < 4; c++) {  // 4 chunks of K=64
        int s = c & 1;
        if (c + 1 < 4) {
            int sn = (c + 1) & 1;
            const __nv_bfloat16* Ap = Arow + (c + 1) * 64;
            const __nv_bfloat16* Bp = Brow + (c + 1) * 64;
#pragma unroll
            for (int s4 = 0; s4 < 4; s4++) {
                CP_ASYNC16(dA + sn * stage + s4 * 16, Ap + s4 * 8);
                CP_ASYNC16(dB + sn * stage + s4 * 16, Bp + s4 * 8);
            }
        }
        CP_COMMIT();
        CP_WAIT1();
        __syncthreads();

        uint32_t bA = sA0 + s * stage, bB = sB0 + s * stage;
#pragma unroll
        for (int kh = 0; kh < 4; kh++) {
            uint32_t af[2][4], bfr[2][4];
#pragma unroll
            for (int mt = 0; mt < 2; mt++) ldm_x4(af[mt], bA + a_off[mt] + kh * 32);
#pragma unroll
            for (int np = 0; np < 2; np++) ldm_x4(bfr[np], bB + b_off[np] + kh * 32);
#pragma unroll
            for (int mt = 0; mt < 2; mt++)
#pragma unroll
                for (int nt = 0; nt < 4; nt++)
                    mma_bf16(acc[mt][nt], af[mt], &bfr[nt >> 1][(nt & 1) * 2]);
        }
        __syncthreads();
    }

    int grp = lane >> 2, qp = lane & 3;
#pragma unroll
    for (int mt = 0; mt < 2; mt++)
#pragma unroll
        for (int half = 0; half < 2; half++) {
            int row = ti * 64 + warp_m * 32 + mt * 16 + grp + half * 8;
#pragma unroll
            for (int nt = 0; nt < 4; nt++) {
                int col = tj * 64 + warp_n * 32 + nt * 8 + qp * 2;
                float v0 = acc[mt][nt][half * 2];
                float v1 = acc[mt][nt][half * 2 + 1];
                if (tEpi) {
                    v0 = ((row == col) ? 1.5f : 0.f) - 0.5f * v0;
                    v1 = ((row == col + 1) ? 1.5f : 0.f) - 0.5f * v1;
                }
                __nv_bfloat162 hv;
                hv.x = __float2bfloat16(v0);
                hv.y = __float2bfloat16(v1);
                size_t o = boff + (size_t)row * CH + col;
                *(__nv_bfloat162*)(C + o) = hv;
                if (Cf) *(float2*)(Cf + o) = make_float2(v0, v1);
            }
        }
}

// T = 1.5I - 0.5 * Z@Y
__global__ void __launch_bounds__(128) nsT_kernel(int cur) {
    ns_mm_body(g_Zh[cur], g_Yh[cur], g_Th, nullptr, true);
}
// z=0: Ynew = Y@T ; z=1: Znew = Z@T
__global__ void __launch_bounds__(128) nsYZ_kernel(int cur) {
    int z = blockIdx.z;
    const __nv_bfloat16* A = z ? g_Zh[cur] : g_Yh[cur];
    __nv_bfloat16* C = z ? g_Zh[cur ^ 1] : g_Yh[cur ^ 1];
    ns_mm_body(A, g_Th, C, nullptr, false);
}
// final iteration: only Z is needed; emit fp32 Z for the rowmean
__global__ void __launch_bounds__(128) nsZlast_kernel(int cur) {
    ns_mm_body(g_Zh[cur], g_Th, g_Zh[cur ^ 1], g_Zf, false);
}

// ---------------- fused rowmean(Z)/sqrt(normA) + SE MLP + sigmoid ----------------
__global__ void __launch_bounds__(256) rowmean_se_kernel(
    const float* __restrict__ w1, const float* __restrict__ b1,
    const float* __restrict__ w2, const float* __restrict__ b2) {
    int b = blockIdx.x, c = threadIdx.x;
    __shared__ float ys[CH];
    __shared__ float hs[32];
    const float4* row = (const float4*)(g_Zf + ((size_t)b * CH + c) * CH);
    float s = 0.f;
#pragma unroll 8
    for (int d = 0; d < CH / 4; d++) {
        float4 v = row[d];
        s += v.x + v.y + v.z + v.w;
    }
    ys[c] = s * (1.f / CH) * g_rs[b];
    __syncthreads();
    if (c < 32) {
        float h = b1[c];
        const float* w = w1 + c * CH;
#pragma unroll 8
        for (int j = 0; j < CH; j++) h = fmaf(ys[j], w[j], h);
        hs[c] = fmaxf(h, 0.f);
    }
    __syncthreads();
    float g = b2[c];
    const float* w = w2 + c * 32;
#pragma unroll
    for (int j = 0; j < 32; j++) g = fmaf(hs[j], w[j], g);
    g_gate[b * CH + c] = 1.f / (1.f + expf(-g));
}

// ---------------- out = x * gate[b,c] ----------------
__global__ void __launch_bounds__(256) scale_kernel(const float* __restrict__ x,
                                                    float* __restrict__ out) {
    const float4* xi = (const float4*)x;
    float4* oo = (float4*)out;
    const size_t total = (size_t)BATCH * CH * MSP / 4;
    for (size_t i = (size_t)blockIdx.x * blockDim.x + threadIdx.x; i < total;
         i += (size_t)gridDim.x * blockDim.x) {
        float g = g_gate[i >> 12];
        float4 v = xi[i];
        v.x *= g; v.y *= g; v.z *= g; v.w *= g;
        oo[i] = v;
    }
}

// ---------------- launch ----------------
extern "C" void kernel_launch(void* const* d_in, const int* in_sizes, int n_in,
                              void* d_out, int out_size) {
    const float* x = (const float*)d_in[0];
    const float* w1 = (const float*)d_in[1];
    const float* b1 = (const float*)d_in[2];
    const float* w2 = (const float*)d_in[3];
    const float* b2 = (const float*)d_in[4];
    float* out = (float*)d_out;

    convert_kernel<<<BATCH * CH, 256>>>(x);
    gram_hmma_kernel<<<dim3(3, KSG, BATCH), 256>>>();
    cov_reduce_kernel<<<dim3(256, BATCH), 256>>>();
    init_frob_kernel<<<dim3(256, BATCH), 256>>>();

    int cur = 0;
    for (int it = 0; it < 4; it++) {
        nsT_kernel<<<dim3(16, BATCH), 128>>>(cur);
        nsYZ_kernel<<<dim3(16, BATCH, 2), 128>>>(cur);
        cur ^= 1;
    }
    nsT_kernel<<<dim3(16, BATCH), 128>>>(cur);
    nsZlast_kernel<<<dim3(16, BATCH), 128>>>(cur);

    rowmean_se_kernel<<<BATCH, 256>>>(w1, b1, w2, b2);
    scale_kernel<<<8192, 256>>>(x, out);
}